// round 11
// baseline (speedup 1.0000x reference)
#include <cuda_runtime.h>
#include <cuda_fp16.h>
#include <mma.h>

using namespace nvcuda;

constexpr int L_ = 2048, H_ = 8, GSTR = 512;
constexpr int LDH = 72;   // f16 tile leading dim (halves)
constexpr int LDF = 68;   // f32 tile leading dim
constexpr int TSZ = 9216; // one 64x72 f16 tile, bytes
constexpr int OQH = 0,      OQL = 9216;
constexpr int OKH0 = 18432;                 // Khi double buffer [2]
constexpr int OVH0 = 36864, OVL0 = 46080;   // V buffer 0
constexpr int OVH1 = 55296, OVL1 = 64512;   // V buffer 1
constexpr int OPH = 73728;
constexpr int OSF = 82944, ODS = 100352;
constexpr int SM_BYTES = 100864;

// gmem f32 64x64 -> hi+lo f16 tiles. t in [0,256).
__device__ __forceinline__ void fill_hilo(const float* g, __half* hi, __half* lo, int t)
{
    #pragma unroll
    for (int i = 0; i < 2; i++) {
        int ck = i * 256 + t;
        int row = ck >> 3, ch = (ck & 7) * 8;
        const float* s = g + (size_t)row * GSTR + ch;
        float4 x = *(const float4*)s;
        float4 y = *(const float4*)(s + 4);
        float xs[8] = {x.x, x.y, x.z, x.w, y.x, y.y, y.z, y.w};
        __align__(16) __half2 hh[4];
        __align__(16) __half2 ll[4];
        #pragma unroll
        for (int j = 0; j < 4; j++) {
            __half2 a = __floats2half2_rn(xs[2 * j], xs[2 * j + 1]);
            float2 f = __half22float2(a);
            hh[j] = a;
            ll[j] = __floats2half2_rn(xs[2 * j] - f.x, xs[2 * j + 1] - f.y);
        }
        *(uint4*)&hi[row * LDH + ch] = *(uint4*)hh;
        *(uint4*)&lo[row * LDH + ch] = *(uint4*)ll;
    }
}

// gmem f32 64x64 -> hi-only f16 tile. t in [0,256).
__device__ __forceinline__ void fill_hi(const float* g, __half* hi, int t)
{
    #pragma unroll
    for (int i = 0; i < 2; i++) {
        int ck = i * 256 + t;
        int row = ck >> 3, ch = (ck & 7) * 8;
        const float* s = g + (size_t)row * GSTR + ch;
        float4 x = *(const float4*)s;
        float4 y = *(const float4*)(s + 4);
        __align__(16) __half2 hh[4];
        hh[0] = __floats2half2_rn(x.x, x.y);
        hh[1] = __floats2half2_rn(x.z, x.w);
        hh[2] = __floats2half2_rn(y.x, y.y);
        hh[3] = __floats2half2_rn(y.z, y.w);
        *(uint4*)&hi[row * LDH + ch] = *(uint4*)hh;
    }
}

__global__ void __launch_bounds__(256, 2)
attn_kernel(const float* __restrict__ Q, const float* __restrict__ K,
            const float* __restrict__ V, const float* __restrict__ tau,
            const float* __restrict__ delta, float* __restrict__ O)
{
    extern __shared__ char smc[];
    __half* Qhi = (__half*)(smc + OQH);
    __half* Qlo = (__half*)(smc + OQL);
    __half* Phi = (__half*)(smc + OPH);
    float*  Sf  = (float*)(smc + OSF);
    float*  Ds  = (float*)(smc + ODS);   // [2][64]

    const int qt = blockIdx.x, bh = blockIdx.y, b = bh >> 3, h = bh & 7;
    const int t = threadIdx.x, w = t >> 5;
    const int wr = w >> 1, wc = w & 1;       // warp block: rows [16wr,+16), cols [32wc,+32)
    const int r = t >> 2, cb = (t & 3) * 16; // softmax: row r, cols [cb,cb+16)
    const int srow = ((t >> 3) /*0..31 -> rows via ck*/), sch = (t & 7) * 8; // staging row/col for i=0

    const float stl = 0.125f * tau[b];
    const float sdl = 0.125f;

    const float* qg = Q + ((size_t)(b * L_ + qt * 64) * H_ + h) * 64;
    const float* kg = K + ((size_t)(b * L_) * H_ + h) * 64;
    const float* vg = V + ((size_t)(b * L_) * H_ + h) * 64;
    const float* dg = delta + (size_t)b * L_;

    // prologue: Q (hi/lo), K0, V0, Ds0
    fill_hilo(qg, Qhi, Qlo, t);
    fill_hi(kg, (__half*)(smc + OKH0), t);
    fill_hilo(vg, (__half*)(smc + OVH0), (__half*)(smc + OVL0), t);
    if (t < 64) Ds[t] = dg[t] * sdl;

    wmma::fragment<wmma::accumulator, 16, 16, 16, float> oacc[2];
    wmma::fill_fragment(oacc[0], 0.0f);
    wmma::fill_fragment(oacc[1], 0.0f);
    float lsum = 0.0f;

    for (int kt = 0; kt <= qt; kt++) {
        __syncthreads();   // staged tiles visible; prior buffer reads complete
        const int cur = kt & 1, nxt = cur ^ 1;
        __half* KhiC = (__half*)(smc + OKH0 + cur * TSZ);
        __half* KhiN = (__half*)(smc + OKH0 + nxt * TSZ);
        __half* VhiC = (__half*)(smc + (cur ? OVH1 : OVH0));
        __half* VloC = (__half*)(smc + (cur ? OVL1 : OVL0));
        __half* VhiN = (__half*)(smc + (nxt ? OVH1 : OVH0));
        __half* VloN = (__half*)(smc + (nxt ? OVL1 : OVL0));
        const bool pre = (kt < qt);
        const float* gk = kg + (size_t)(kt + 1) * 64 * GSTR;
        const float* gv = vg + (size_t)(kt + 1) * 64 * GSTR;

        // ---- stage K(kt+1) + delta(kt+1) into registers ----
        float4 kst[4];
        float dreg = 0.0f;
        if (pre) {
            #pragma unroll
            for (int i = 0; i < 2; i++) {
                int ck = i * 256 + t;
                int row = ck >> 3, ch = (ck & 7) * 8;
                const float* s = gk + (size_t)row * GSTR + ch;
                kst[2 * i]     = *(const float4*)s;
                kst[2 * i + 1] = *(const float4*)(s + 4);
            }
            if (t < 64) dreg = dg[(kt + 1) * 64 + t] * sdl;
        }

        // ---- QK^T: (Qhi+Qlo)*Khi, warp 16x32 block ----
        {
            wmma::fragment<wmma::accumulator, 16, 16, 16, float> acc[2];
            wmma::fill_fragment(acc[0], 0.0f);
            wmma::fill_fragment(acc[1], 0.0f);
            #pragma unroll
            for (int k = 0; k < 4; k++) {
                wmma::fragment<wmma::matrix_a, 16, 16, 16, __half, wmma::row_major> aH, aL;
                wmma::load_matrix_sync(aH, Qhi + wr * 16 * LDH + k * 16, LDH);
                wmma::load_matrix_sync(aL, Qlo + wr * 16 * LDH + k * 16, LDH);
                #pragma unroll
                for (int n = 0; n < 2; n++) {
                    wmma::fragment<wmma::matrix_b, 16, 16, 16, __half, wmma::col_major> bH;
                    wmma::load_matrix_sync(bH, KhiC + (wc * 32 + n * 16) * LDH + k * 16, LDH);
                    wmma::mma_sync(acc[n], aH, bH, acc[n]);
                    wmma::mma_sync(acc[n], aL, bH, acc[n]);
                }
            }
            wmma::store_matrix_sync(Sf + wr * 16 * LDF + wc * 32,      acc[0], LDF, wmma::mem_row_major);
            wmma::store_matrix_sync(Sf + wr * 16 * LDF + wc * 32 + 16, acc[1], LDF, wmma::mem_row_major);
        }

        // ---- convert staged K -> Khi[nxt]; stage V(kt+1) loads ----
        float4 vst[4];
        if (pre) {
            #pragma unroll
            for (int i = 0; i < 2; i++) {
                int ck = i * 256 + t;
                int row = ck >> 3, ch = (ck & 7) * 8;
                __align__(16) __half2 hh[4];
                hh[0] = __floats2half2_rn(kst[2 * i].x,     kst[2 * i].y);
                hh[1] = __floats2half2_rn(kst[2 * i].z,     kst[2 * i].w);
                hh[2] = __floats2half2_rn(kst[2 * i + 1].x, kst[2 * i + 1].y);
                hh[3] = __floats2half2_rn(kst[2 * i + 1].z, kst[2 * i + 1].w);
                *(uint4*)&KhiN[row * LDH + ch] = *(uint4*)hh;
                const float* s = gv + (size_t)row * GSTR + ch;
                vst[2 * i]     = *(const float4*)s;
                vst[2 * i + 1] = *(const float4*)(s + 4);
            }
        }
        __syncthreads();

        // ---- softmax (bounded logits): row r, cols [cb,cb+16) ----
        {
            const int qr = qt * 64 + r;
            const int s0 = kt * 64;
            const bool diag = (kt == qt);
            const float* DsC = Ds + cur * 64;
            float psum = 0.0f;
            #pragma unroll
            for (int j = 0; j < 16; j += 4) {
                float4 sv = *(const float4*)&Sf[r * LDF + cb + j];
                float z0 = sv.x * stl + DsC[cb + j];
                float z1 = sv.y * stl + DsC[cb + j + 1];
                float z2 = sv.z * stl + DsC[cb + j + 2];
                float z3 = sv.w * stl + DsC[cb + j + 3];
                if (diag) {
                    if (s0 + cb + j     > qr) z0 = -1e30f;
                    if (s0 + cb + j + 1 > qr) z1 = -1e30f;
                    if (s0 + cb + j + 2 > qr) z2 = -1e30f;
                    if (s0 + cb + j + 3 > qr) z3 = -1e30f;
                }
                float p0 = __expf(z0), p1 = __expf(z1);
                float p2 = __expf(z2), p3 = __expf(z3);
                psum += (p0 + p1) + (p2 + p3);
                __align__(8) __half2 hp[2];
                hp[0] = __floats2half2_rn(p0, p1);
                hp[1] = __floats2half2_rn(p2, p3);
                *(uint2*)&Phi[r * LDH + cb + j] = *(uint2*)hp;
            }
            lsum += psum;
        }
        __syncthreads();

        // ---- convert staged V -> Vhi/Vlo[nxt]; write Ds[nxt] ----
        if (pre) {
            #pragma unroll
            for (int i = 0; i < 2; i++) {
                int ck = i * 256 + t;
                int row = ck >> 3, ch = (ck & 7) * 8;
                float xs[8] = {vst[2*i].x, vst[2*i].y, vst[2*i].z, vst[2*i].w,
                               vst[2*i+1].x, vst[2*i+1].y, vst[2*i+1].z, vst[2*i+1].w};
                __align__(16) __half2 hh[4];
                __align__(16) __half2 ll[4];
                #pragma unroll
                for (int j = 0; j < 4; j++) {
                    __half2 a = __floats2half2_rn(xs[2 * j], xs[2 * j + 1]);
                    float2 f = __half22float2(a);
                    hh[j] = a;
                    ll[j] = __floats2half2_rn(xs[2 * j] - f.x, xs[2 * j + 1] - f.y);
                }
                *(uint4*)&VhiN[row * LDH + ch] = *(uint4*)hh;
                *(uint4*)&VloN[row * LDH + ch] = *(uint4*)ll;
            }
            if (t < 64) Ds[nxt * 64 + t] = dreg;
        }

        // ---- P @ V: Phi*(Vhi+Vlo). Persistent O fragments ----
        #pragma unroll
        for (int k = 0; k < 4; k++) {
            wmma::fragment<wmma::matrix_a, 16, 16, 16, __half, wmma::row_major> pH;
            wmma::load_matrix_sync(pH, Phi + wr * 16 * LDH + k * 16, LDH);
            #pragma unroll
            for (int n = 0; n < 2; n++) {
                wmma::fragment<wmma::matrix_b, 16, 16, 16, __half, wmma::row_major> vH, vL;
                wmma::load_matrix_sync(vH, VhiC + k * 16 * LDH + wc * 32 + n * 16, LDH);
                wmma::load_matrix_sync(vL, VloC + k * 16 * LDH + wc * 32 + n * 16, LDH);
                wmma::mma_sync(oacc[n], pH, vH, oacc[n]);
                wmma::mma_sync(oacc[n], pH, vL, oacc[n]);
            }
        }
    }

    // ---- epilogue ----
    __syncthreads();
    wmma::store_matrix_sync(Sf + wr * 16 * LDF + wc * 32,      oacc[0], LDF, wmma::mem_row_major);
    wmma::store_matrix_sync(Sf + wr * 16 * LDF + wc * 32 + 16, oacc[1], LDF, wmma::mem_row_major);
    __syncthreads();

    lsum += __shfl_xor_sync(0xFFFFFFFFu, lsum, 1);
    lsum += __shfl_xor_sync(0xFFFFFFFFu, lsum, 2);
    const float inv = 1.0f / lsum;

    float* ob = O + ((size_t)(b * L_ + qt * 64 + r) * H_ + h) * 64 + cb;
    #pragma unroll
    for (int j = 0; j < 16; j += 4) {
        float4 sv = *(const float4*)&Sf[r * LDF + cb + j];
        float4 v;
        v.x = sv.x * inv; v.y = sv.y * inv;
        v.z = sv.z * inv; v.w = sv.w * inv;
        *(float4*)&ob[j] = v;
    }
}

extern "C" void kernel_launch(void* const* d_in, const int* in_sizes, int n_in,
                              void* d_out, int out_size)
{
    cudaFuncSetAttribute(attn_kernel,
                         cudaFuncAttributeMaxDynamicSharedMemorySize, SM_BYTES);
    dim3 grid(L_ / 64, 32);
    attn_kernel<<<grid, 256, SM_BYTES>>>(
        (const float*)d_in[0], (const float*)d_in[1], (const float*)d_in[2],
        (const float*)d_in[3], (const float*)d_in[4], (float*)d_out);
}

// round 13
// speedup vs baseline: 1.0848x; 1.0848x over previous
#include <cuda_runtime.h>
#include <cuda_fp16.h>
#include <mma.h>

using namespace nvcuda;

constexpr int L_ = 2048, H_ = 8, GSTR = 512;
constexpr int LDH = 72;   // f16 tile leading dim (halves)
constexpr int LDF = 68;   // f32 tile leading dim
constexpr int OQH = 0,     OQL = 9216,  OKH = 18432;
constexpr int OVH = 27648, OVL = 36864, OPH = 46080;
constexpr int OSF = 55296, ODS = 72704;
constexpr int SM_BYTES = 72960;

// gmem f32 64x64 -> hi+lo f16 tiles, dense warp-level LDG. t in [0,256).
// 1024 float4 chunks: 16 per row, 64 rows.
__device__ __forceinline__ void fill_hilo(const float* g, __half* hi, __half* lo, int t)
{
    #pragma unroll
    for (int j = 0; j < 4; j++) {
        int c = j * 256 + t;               // 0..1023
        int row = c >> 4, col = (c & 15) * 4;
        float4 x = *(const float4*)(g + (size_t)row * GSTR + col);
        __half2 h0 = __floats2half2_rn(x.x, x.y);
        __half2 h1 = __floats2half2_rn(x.z, x.w);
        float2 f0 = __half22float2(h0), f1 = __half22float2(h1);
        __align__(8) __half2 hh[2];
        __align__(8) __half2 ll[2];
        hh[0] = h0; hh[1] = h1;
        ll[0] = __floats2half2_rn(x.x - f0.x, x.y - f0.y);
        ll[1] = __floats2half2_rn(x.z - f1.x, x.w - f1.y);
        *(uint2*)&hi[row * LDH + col] = *(uint2*)hh;
        *(uint2*)&lo[row * LDH + col] = *(uint2*)ll;
    }
}

// gmem f32 64x64 -> hi-only f16 tile, dense warp-level LDG. t in [0,256).
__device__ __forceinline__ void fill_hi(const float* g, __half* hi, int t)
{
    #pragma unroll
    for (int j = 0; j < 4; j++) {
        int c = j * 256 + t;               // 0..1023
        int row = c >> 4, col = (c & 15) * 4;
        float4 x = *(const float4*)(g + (size_t)row * GSTR + col);
        __align__(8) __half2 hh[2];
        hh[0] = __floats2half2_rn(x.x, x.y);
        hh[1] = __floats2half2_rn(x.z, x.w);
        *(uint2*)&hi[row * LDH + col] = *(uint2*)hh;
    }
}

__global__ void __launch_bounds__(256, 2)
attn_kernel(const float* __restrict__ Q, const float* __restrict__ K,
            const float* __restrict__ V, const float* __restrict__ tau,
            const float* __restrict__ delta, float* __restrict__ O)
{
    extern __shared__ char smc[];
    __half* Qhi = (__half*)(smc + OQH);
    __half* Qlo = (__half*)(smc + OQL);
    __half* Khi = (__half*)(smc + OKH);
    __half* Vhi = (__half*)(smc + OVH);
    __half* Vlo = (__half*)(smc + OVL);
    __half* Phi = (__half*)(smc + OPH);
    float*  Sf  = (float*)(smc + OSF);
    float*  Ds  = (float*)(smc + ODS);

    const int qt = blockIdx.x, bh = blockIdx.y, b = bh >> 3, h = bh & 7;
    const int t = threadIdx.x, w = t >> 5;
    const int wr = w >> 1, wc = w & 1;       // warp block: rows [16wr,+16), cols [32wc,+32)
    const int r = t >> 2, cb = (t & 3) * 16; // softmax: row r, cols [cb,cb+16)

    const float stl = 0.125f * tau[b];       // natural-log domain (__expf)
    const float sdl = 0.125f;

    const float* qg = Q + ((size_t)(b * L_ + qt * 64) * H_ + h) * 64;
    const float* kg = K + ((size_t)(b * L_) * H_ + h) * 64;
    const float* vg = V + ((size_t)(b * L_) * H_ + h) * 64;
    const float* dg = delta + (size_t)b * L_;

    fill_hilo(qg, Qhi, Qlo, t);

    wmma::fragment<wmma::accumulator, 16, 16, 16, float> oacc[2];
    wmma::fill_fragment(oacc[0], 0.0f);
    wmma::fill_fragment(oacc[1], 0.0f);
    float lsum = 0.0f;

    for (int kt = 0; kt <= qt; kt++) {
        __syncthreads();
        fill_hi(kg + (size_t)kt * 64 * GSTR, Khi, t);
        fill_hilo(vg + (size_t)kt * 64 * GSTR, Vhi, Vlo, t);
        if (t < 64) Ds[t] = dg[kt * 64 + t] * sdl;
        __syncthreads();

        // ---- QK^T: (Qhi+Qlo)*Khi, exact in q. Warp: 16x32 block ----
        {
            wmma::fragment<wmma::accumulator, 16, 16, 16, float> acc[2];
            wmma::fill_fragment(acc[0], 0.0f);
            wmma::fill_fragment(acc[1], 0.0f);
            #pragma unroll
            for (int k = 0; k < 4; k++) {
                wmma::fragment<wmma::matrix_a, 16, 16, 16, __half, wmma::row_major> aH, aL;
                wmma::load_matrix_sync(aH, Qhi + wr * 16 * LDH + k * 16, LDH);
                wmma::load_matrix_sync(aL, Qlo + wr * 16 * LDH + k * 16, LDH);
                #pragma unroll
                for (int n = 0; n < 2; n++) {
                    wmma::fragment<wmma::matrix_b, 16, 16, 16, __half, wmma::col_major> bH;
                    wmma::load_matrix_sync(bH, Khi + (wc * 32 + n * 16) * LDH + k * 16, LDH);
                    wmma::mma_sync(acc[n], aH, bH, acc[n]);
                    wmma::mma_sync(acc[n], aL, bH, acc[n]);
                }
            }
            wmma::store_matrix_sync(Sf + wr * 16 * LDF + wc * 32,      acc[0], LDF, wmma::mem_row_major);
            wmma::store_matrix_sync(Sf + wr * 16 * LDF + wc * 32 + 16, acc[1], LDF, wmma::mem_row_major);
        }
        __syncthreads();

        // ---- softmax (bounded logits, no max-sub): row r, cols [cb,cb+16) ----
        {
            const int qr = qt * 64 + r;
            const int s0 = kt * 64;
            const bool diag = (kt == qt);
            float psum = 0.0f;
            #pragma unroll
            for (int j = 0; j < 16; j += 4) {
                float4 sv = *(const float4*)&Sf[r * LDF + cb + j];
                float z0 = sv.x * stl + Ds[cb + j];
                float z1 = sv.y * stl + Ds[cb + j + 1];
                float z2 = sv.z * stl + Ds[cb + j + 2];
                float z3 = sv.w * stl + Ds[cb + j + 3];
                if (diag) {
                    if (s0 + cb + j     > qr) z0 = -1e30f;
                    if (s0 + cb + j + 1 > qr) z1 = -1e30f;
                    if (s0 + cb + j + 2 > qr) z2 = -1e30f;
                    if (s0 + cb + j + 3 > qr) z3 = -1e30f;
                }
                float p0 = __expf(z0), p1 = __expf(z1);
                float p2 = __expf(z2), p3 = __expf(z3);
                psum += (p0 + p1) + (p2 + p3);
                __align__(8) __half2 hp[2];
                hp[0] = __floats2half2_rn(p0, p1);
                hp[1] = __floats2half2_rn(p2, p3);
                *(uint2*)&Phi[r * LDH + cb + j] = *(uint2*)hp;
            }
            lsum += psum;
        }
        __syncthreads();

        // ---- P @ V: Phi*(Vhi+Vlo), exact in v. Persistent O fragments ----
        #pragma unroll
        for (int k = 0; k < 4; k++) {
            wmma::fragment<wmma::matrix_a, 16, 16, 16, __half, wmma::row_major> pH;
            wmma::load_matrix_sync(pH, Phi + wr * 16 * LDH + k * 16, LDH);
            #pragma unroll
            for (int n = 0; n < 2; n++) {
                wmma::fragment<wmma::matrix_b, 16, 16, 16, __half, wmma::row_major> vH, vL;
                wmma::load_matrix_sync(vH, Vhi + k * 16 * LDH + wc * 32 + n * 16, LDH);
                wmma::load_matrix_sync(vL, Vlo + k * 16 * LDH + wc * 32 + n * 16, LDH);
                wmma::mma_sync(oacc[n], pH, vH, oacc[n]);
                wmma::mma_sync(oacc[n], pH, vL, oacc[n]);
            }
        }
    }

    // ---- epilogue ----
    wmma::store_matrix_sync(Sf + wr * 16 * LDF + wc * 32,      oacc[0], LDF, wmma::mem_row_major);
    wmma::store_matrix_sync(Sf + wr * 16 * LDF + wc * 32 + 16, oacc[1], LDF, wmma::mem_row_major);
    __syncthreads();

    lsum += __shfl_xor_sync(0xFFFFFFFFu, lsum, 1);
    lsum += __shfl_xor_sync(0xFFFFFFFFu, lsum, 2);
    const float inv = 1.0f / lsum;

    float* ob = O + ((size_t)(b * L_ + qt * 64 + r) * H_ + h) * 64 + cb;
    #pragma unroll
    for (int j = 0; j < 16; j += 4) {
        float4 sv = *(const float4*)&Sf[r * LDF + cb + j];
        float4 v;
        v.x = sv.x * inv; v.y = sv.y * inv;
        v.z = sv.z * inv; v.w = sv.w * inv;
        *(float4*)&ob[j] = v;
    }
}

extern "C" void kernel_launch(void* const* d_in, const int* in_sizes, int n_in,
                              void* d_out, int out_size)
{
    cudaFuncSetAttribute(attn_kernel,
                         cudaFuncAttributeMaxDynamicSharedMemorySize, SM_BYTES);
    dim3 grid(L_ / 64, 32);
    attn_kernel<<<grid, 256, SM_BYTES>>>(
        (const float*)d_in[0], (const float*)d_in[1], (const float*)d_in[2],
        (const float*)d_in[3], (const float*)d_in[4], (float*)d_out);
}

// round 14
// speedup vs baseline: 1.1140x; 1.0269x over previous
#include <cuda_runtime.h>
#include <cuda_fp16.h>
#include <mma.h>

using namespace nvcuda;

constexpr int L_ = 2048, H_ = 8, GSTR = 512;
constexpr int LDH = 72;   // f16 tile leading dim (halves)
constexpr int LDF = 68;   // f32 tile leading dim
constexpr int OQH = 0,     OQL = 9216,  OKH = 18432;
constexpr int OVH = 27648, OPL = 36864, OPH = 46080;
constexpr int OSF = 55296, ODS = 72704;
constexpr int SM_BYTES = 72960;

// gmem f32 64x64 -> hi+lo f16 tiles, dense warp-level LDG. t in [0,256).
__device__ __forceinline__ void fill_hilo(const float* g, __half* hi, __half* lo, int t)
{
    #pragma unroll
    for (int j = 0; j < 4; j++) {
        int c = j * 256 + t;               // 0..1023
        int row = c >> 4, col = (c & 15) * 4;
        float4 x = *(const float4*)(g + (size_t)row * GSTR + col);
        __half2 h0 = __floats2half2_rn(x.x, x.y);
        __half2 h1 = __floats2half2_rn(x.z, x.w);
        float2 f0 = __half22float2(h0), f1 = __half22float2(h1);
        __align__(8) __half2 hh[2];
        __align__(8) __half2 ll[2];
        hh[0] = h0; hh[1] = h1;
        ll[0] = __floats2half2_rn(x.x - f0.x, x.y - f0.y);
        ll[1] = __floats2half2_rn(x.z - f1.x, x.w - f1.y);
        *(uint2*)&hi[row * LDH + col] = *(uint2*)hh;
        *(uint2*)&lo[row * LDH + col] = *(uint2*)ll;
    }
}

// gmem f32 64x64 -> hi-only f16 tile, dense warp-level LDG. t in [0,256).
__device__ __forceinline__ void fill_hi(const float* g, __half* hi, int t)
{
    #pragma unroll
    for (int j = 0; j < 4; j++) {
        int c = j * 256 + t;               // 0..1023
        int row = c >> 4, col = (c & 15) * 4;
        float4 x = *(const float4*)(g + (size_t)row * GSTR + col);
        __align__(8) __half2 hh[2];
        hh[0] = __floats2half2_rn(x.x, x.y);
        hh[1] = __floats2half2_rn(x.z, x.w);
        *(uint2*)&hi[row * LDH + col] = *(uint2*)hh;
    }
}

__global__ void __launch_bounds__(256, 2)
attn_kernel(const float* __restrict__ Q, const float* __restrict__ K,
            const float* __restrict__ V, const float* __restrict__ tau,
            const float* __restrict__ delta, float* __restrict__ O)
{
    extern __shared__ char smc[];
    __half* Qhi = (__half*)(smc + OQH);
    __half* Qlo = (__half*)(smc + OQL);
    __half* Khi = (__half*)(smc + OKH);
    __half* Vhi = (__half*)(smc + OVH);
    __half* Plo = (__half*)(smc + OPL);
    __half* Phi = (__half*)(smc + OPH);
    float*  Sf  = (float*)(smc + OSF);
    float*  Ds  = (float*)(smc + ODS);

    const int qt = (int)gridDim.x - 1 - (int)blockIdx.x;   // longest CTAs first
    const int bh = blockIdx.y, b = bh >> 3, h = bh & 7;
    const int t = threadIdx.x, w = t >> 5;
    const int wr = w >> 1, wc = w & 1;       // warp block: rows [16wr,+16), cols [32wc,+32)
    const int r = t >> 2, cb = (t & 3) * 16; // softmax: row r, cols [cb,cb+16)

    const float stl = 0.125f * tau[b];       // natural-log domain (__expf)
    const float sdl = 0.125f;

    const float* qg = Q + ((size_t)(b * L_ + qt * 64) * H_ + h) * 64;
    const float* kg = K + ((size_t)(b * L_) * H_ + h) * 64;
    const float* vg = V + ((size_t)(b * L_) * H_ + h) * 64;
    const float* dg = delta + (size_t)b * L_;

    fill_hilo(qg, Qhi, Qlo, t);

    wmma::fragment<wmma::accumulator, 16, 16, 16, float> oacc[2];
    wmma::fill_fragment(oacc[0], 0.0f);
    wmma::fill_fragment(oacc[1], 0.0f);
    float lsum = 0.0f;

    for (int kt = 0; kt <= qt; kt++) {
        __syncthreads();
        fill_hi(kg + (size_t)kt * 64 * GSTR, Khi, t);
        fill_hi(vg + (size_t)kt * 64 * GSTR, Vhi, t);
        if (t < 64) Ds[t] = dg[kt * 64 + t] * sdl;
        __syncthreads();

        // ---- QK^T: (Qhi+Qlo)*Khi, exact in q. Warp: 16x32 block ----
        {
            wmma::fragment<wmma::accumulator, 16, 16, 16, float> acc[2];
            wmma::fill_fragment(acc[0], 0.0f);
            wmma::fill_fragment(acc[1], 0.0f);
            #pragma unroll
            for (int k = 0; k < 4; k++) {
                wmma::fragment<wmma::matrix_a, 16, 16, 16, __half, wmma::row_major> aH, aL;
                wmma::load_matrix_sync(aH, Qhi + wr * 16 * LDH + k * 16, LDH);
                wmma::load_matrix_sync(aL, Qlo + wr * 16 * LDH + k * 16, LDH);
                #pragma unroll
                for (int n = 0; n < 2; n++) {
                    wmma::fragment<wmma::matrix_b, 16, 16, 16, __half, wmma::col_major> bH;
                    wmma::load_matrix_sync(bH, Khi + (wc * 32 + n * 16) * LDH + k * 16, LDH);
                    wmma::mma_sync(acc[n], aH, bH, acc[n]);
                    wmma::mma_sync(acc[n], aL, bH, acc[n]);
                }
            }
            wmma::store_matrix_sync(Sf + wr * 16 * LDF + wc * 32,      acc[0], LDF, wmma::mem_row_major);
            wmma::store_matrix_sync(Sf + wr * 16 * LDF + wc * 32 + 16, acc[1], LDF, wmma::mem_row_major);
        }
        __syncthreads();

        // ---- softmax (bounded logits, no max-sub): row r, cols [cb,cb+16) ----
        {
            const int qr = qt * 64 + r;
            const int s0 = kt * 64;
            const bool diag = (kt == qt);
            float psum = 0.0f;
            #pragma unroll
            for (int j = 0; j < 16; j += 4) {
                float4 sv = *(const float4*)&Sf[r * LDF + cb + j];
                float z0 = sv.x * stl + Ds[cb + j];
                float z1 = sv.y * stl + Ds[cb + j + 1];
                float z2 = sv.z * stl + Ds[cb + j + 2];
                float z3 = sv.w * stl + Ds[cb + j + 3];
                if (diag) {
                    if (s0 + cb + j     > qr) z0 = -1e30f;
                    if (s0 + cb + j + 1 > qr) z1 = -1e30f;
                    if (s0 + cb + j + 2 > qr) z2 = -1e30f;
                    if (s0 + cb + j + 3 > qr) z3 = -1e30f;
                }
                float p0 = __expf(z0), p1 = __expf(z1);
                float p2 = __expf(z2), p3 = __expf(z3);
                psum += (p0 + p1) + (p2 + p3);
                __align__(8) __half2 hp[2];
                __align__(8) __half2 lp[2];
                hp[0] = __floats2half2_rn(p0, p1);
                hp[1] = __floats2half2_rn(p2, p3);
                float2 f0 = __half22float2(hp[0]);
                float2 f1 = __half22float2(hp[1]);
                lp[0] = __floats2half2_rn(p0 - f0.x, p1 - f0.y);
                lp[1] = __floats2half2_rn(p2 - f1.x, p3 - f1.y);
                *(uint2*)&Phi[r * LDH + cb + j] = *(uint2*)hp;
                *(uint2*)&Plo[r * LDH + cb + j] = *(uint2*)lp;
            }
            lsum += psum;
        }
        __syncthreads();

        // ---- P @ V: (Phi+Plo)*Vhi, exact in p. Persistent O fragments ----
        #pragma unroll
        for (int k = 0; k < 4; k++) {
            wmma::fragment<wmma::matrix_a, 16, 16, 16, __half, wmma::row_major> pH, pL;
            wmma::load_matrix_sync(pH, Phi + wr * 16 * LDH + k * 16, LDH);
            wmma::load_matrix_sync(pL, Plo + wr * 16 * LDH + k * 16, LDH);
            #pragma unroll
            for (int n = 0; n < 2; n++) {
                wmma::fragment<wmma::matrix_b, 16, 16, 16, __half, wmma::row_major> vH;
                wmma::load_matrix_sync(vH, Vhi + k * 16 * LDH + wc * 32 + n * 16, LDH);
                wmma::mma_sync(oacc[n], pH, vH, oacc[n]);
                wmma::mma_sync(oacc[n], pL, vH, oacc[n]);
            }
        }
    }

    // ---- epilogue ----
    wmma::store_matrix_sync(Sf + wr * 16 * LDF + wc * 32,      oacc[0], LDF, wmma::mem_row_major);
    wmma::store_matrix_sync(Sf + wr * 16 * LDF + wc * 32 + 16, oacc[1], LDF, wmma::mem_row_major);
    __syncthreads();

    lsum += __shfl_xor_sync(0xFFFFFFFFu, lsum, 1);
    lsum += __shfl_xor_sync(0xFFFFFFFFu, lsum, 2);
    const float inv = 1.0f / lsum;

    float* ob = O + ((size_t)(b * L_ + qt * 64 + r) * H_ + h) * 64 + cb;
    #pragma unroll
    for (int j = 0; j < 16; j += 4) {
        float4 sv = *(const float4*)&Sf[r * LDF + cb + j];
        float4 v;
        v.x = sv.x * inv; v.y = sv.y * inv;
        v.z = sv.z * inv; v.w = sv.w * inv;
        *(float4*)&ob[j] = v;
    }
}

extern "C" void kernel_launch(void* const* d_in, const int* in_sizes, int n_in,
                              void* d_out, int out_size)
{
    cudaFuncSetAttribute(attn_kernel,
                         cudaFuncAttributeMaxDynamicSharedMemorySize, SM_BYTES);
    dim3 grid(L_ / 64, 32);
    attn_kernel<<<grid, 256, SM_BYTES>>>(
        (const float*)d_in[0], (const float*)d_in[1], (const float*)d_in[2],
        (const float*)d_in[3], (const float*)d_in[4], (float*)d_out);
}

// round 15
// speedup vs baseline: 1.2518x; 1.1238x over previous
#include <cuda_runtime.h>
#include <cuda_fp16.h>
#include <mma.h>

using namespace nvcuda;

constexpr int L_ = 2048, H_ = 8, GSTR = 512;
constexpr int LDH = 72;   // f16 tile leading dim (halves)
constexpr int LDF = 68;   // f32 tile leading dim
constexpr int OQH = 0,     OQL = 9216,  OKH = 18432;
constexpr int OVH = 27648, OPH = 36864;
constexpr int OSF = 46080, ODS = 63488;
constexpr int SM_BYTES = 63744;

// gmem f32 64x64 -> hi+lo f16 tiles, dense warp-level LDG. t in [0,256).
__device__ __forceinline__ void fill_hilo(const float* g, __half* hi, __half* lo, int t)
{
    #pragma unroll
    for (int j = 0; j < 4; j++) {
        int c = j * 256 + t;               // 0..1023
        int row = c >> 4, col = (c & 15) * 4;
        float4 x = *(const float4*)(g + (size_t)row * GSTR + col);
        __half2 h0 = __floats2half2_rn(x.x, x.y);
        __half2 h1 = __floats2half2_rn(x.z, x.w);
        float2 f0 = __half22float2(h0), f1 = __half22float2(h1);
        __align__(8) __half2 hh[2];
        __align__(8) __half2 ll[2];
        hh[0] = h0; hh[1] = h1;
        ll[0] = __floats2half2_rn(x.x - f0.x, x.y - f0.y);
        ll[1] = __floats2half2_rn(x.z - f1.x, x.w - f1.y);
        *(uint2*)&hi[row * LDH + col] = *(uint2*)hh;
        *(uint2*)&lo[row * LDH + col] = *(uint2*)ll;
    }
}

// gmem f32 64x64 -> hi-only f16 tile, dense warp-level LDG. t in [0,256).
__device__ __forceinline__ void fill_hi(const float* g, __half* hi, int t)
{
    #pragma unroll
    for (int j = 0; j < 4; j++) {
        int c = j * 256 + t;               // 0..1023
        int row = c >> 4, col = (c & 15) * 4;
        float4 x = *(const float4*)(g + (size_t)row * GSTR + col);
        __align__(8) __half2 hh[2];
        hh[0] = __floats2half2_rn(x.x, x.y);
        hh[1] = __floats2half2_rn(x.z, x.w);
        *(uint2*)&hi[row * LDH + col] = *(uint2*)hh;
    }
}

__global__ void __launch_bounds__(256, 2)
attn_kernel(const float* __restrict__ Q, const float* __restrict__ K,
            const float* __restrict__ V, const float* __restrict__ tau,
            const float* __restrict__ delta, float* __restrict__ O)
{
    extern __shared__ char smc[];
    __half* Qhi = (__half*)(smc + OQH);
    __half* Qlo = (__half*)(smc + OQL);
    __half* Khi = (__half*)(smc + OKH);
    __half* Vhi = (__half*)(smc + OVH);
    __half* Phi = (__half*)(smc + OPH);
    float*  Sf  = (float*)(smc + OSF);
    float*  Ds  = (float*)(smc + ODS);

    const int qt = (int)gridDim.x - 1 - (int)blockIdx.x;   // longest CTAs first
    const int bh = blockIdx.y, b = bh >> 3, h = bh & 7;
    const int t = threadIdx.x, w = t >> 5;
    const int wr = w >> 1, wc = w & 1;       // warp block: rows [16wr,+16), cols [32wc,+32)
    const int r = t >> 2, cb = (t & 3) * 16; // softmax: row r, cols [cb,cb+16)

    const float stl = 0.125f * tau[b];       // natural-log domain (__expf)
    const float sdl = 0.125f;

    const float* qg = Q + ((size_t)(b * L_ + qt * 64) * H_ + h) * 64;
    const float* kg = K + ((size_t)(b * L_) * H_ + h) * 64;
    const float* vg = V + ((size_t)(b * L_) * H_ + h) * 64;
    const float* dg = delta + (size_t)b * L_;

    fill_hilo(qg, Qhi, Qlo, t);

    wmma::fragment<wmma::accumulator, 16, 16, 16, float> oacc[2];
    wmma::fill_fragment(oacc[0], 0.0f);
    wmma::fill_fragment(oacc[1], 0.0f);
    float lsum = 0.0f;

    for (int kt = 0; kt <= qt; kt++) {
        __syncthreads();
        fill_hi(kg + (size_t)kt * 64 * GSTR, Khi, t);
        fill_hi(vg + (size_t)kt * 64 * GSTR, Vhi, t);
        if (t < 64) Ds[t] = dg[kt * 64 + t] * sdl;
        __syncthreads();

        // ---- QK^T: (Qhi+Qlo)*Khi, exact in q. Warp: 16x32 block ----
        {
            wmma::fragment<wmma::accumulator, 16, 16, 16, float> acc[2];
            wmma::fill_fragment(acc[0], 0.0f);
            wmma::fill_fragment(acc[1], 0.0f);
            #pragma unroll
            for (int k = 0; k < 4; k++) {
                wmma::fragment<wmma::matrix_a, 16, 16, 16, __half, wmma::row_major> aH, aL;
                wmma::load_matrix_sync(aH, Qhi + wr * 16 * LDH + k * 16, LDH);
                wmma::load_matrix_sync(aL, Qlo + wr * 16 * LDH + k * 16, LDH);
                #pragma unroll
                for (int n = 0; n < 2; n++) {
                    wmma::fragment<wmma::matrix_b, 16, 16, 16, __half, wmma::col_major> bH;
                    wmma::load_matrix_sync(bH, Khi + (wc * 32 + n * 16) * LDH + k * 16, LDH);
                    wmma::mma_sync(acc[n], aH, bH, acc[n]);
                    wmma::mma_sync(acc[n], aL, bH, acc[n]);
                }
            }
            wmma::store_matrix_sync(Sf + wr * 16 * LDF + wc * 32,      acc[0], LDF, wmma::mem_row_major);
            wmma::store_matrix_sync(Sf + wr * 16 * LDF + wc * 32 + 16, acc[1], LDF, wmma::mem_row_major);
        }
        __syncthreads();

        // ---- softmax (bounded logits, no max-sub): row r, cols [cb,cb+16) ----
        {
            const int qr = qt * 64 + r;
            const int s0 = kt * 64;
            const bool diag = (kt == qt);
            float psum = 0.0f;
            #pragma unroll
            for (int j = 0; j < 16; j += 4) {
                float4 sv = *(const float4*)&Sf[r * LDF + cb + j];
                float z0 = sv.x * stl + Ds[cb + j];
                float z1 = sv.y * stl + Ds[cb + j + 1];
                float z2 = sv.z * stl + Ds[cb + j + 2];
                float z3 = sv.w * stl + Ds[cb + j + 3];
                if (diag) {
                    if (s0 + cb + j     > qr) z0 = -1e30f;
                    if (s0 + cb + j + 1 > qr) z1 = -1e30f;
                    if (s0 + cb + j + 2 > qr) z2 = -1e30f;
                    if (s0 + cb + j + 3 > qr) z3 = -1e30f;
                }
                float p0 = __expf(z0), p1 = __expf(z1);
                float p2 = __expf(z2), p3 = __expf(z3);
                psum += (p0 + p1) + (p2 + p3);
                __align__(8) __half2 hp[2];
                hp[0] = __floats2half2_rn(p0, p1);
                hp[1] = __floats2half2_rn(p2, p3);
                *(uint2*)&Phi[r * LDH + cb + j] = *(uint2*)hp;
            }
            lsum += psum;
        }
        __syncthreads();

        // ---- P @ V: Phi*Vhi (P,V quant errors negligible per R7/R10/R14) ----
        #pragma unroll
        for (int k = 0; k < 4; k++) {
            wmma::fragment<wmma::matrix_a, 16, 16, 16, __half, wmma::row_major> pH;
            wmma::load_matrix_sync(pH, Phi + wr * 16 * LDH + k * 16, LDH);
            #pragma unroll
            for (int n = 0; n < 2; n++) {
                wmma::fragment<wmma::matrix_b, 16, 16, 16, __half, wmma::row_major> vH;
                wmma::load_matrix_sync(vH, Vhi + k * 16 * LDH + wc * 32 + n * 16, LDH);
                wmma::mma_sync(oacc[n], pH, vH, oacc[n]);
            }
        }
    }

    // ---- epilogue ----
    wmma::store_matrix_sync(Sf + wr * 16 * LDF + wc * 32,      oacc[0], LDF, wmma::mem_row_major);
    wmma::store_matrix_sync(Sf + wr * 16 * LDF + wc * 32 + 16, oacc[1], LDF, wmma::mem_row_major);
    __syncthreads();

    lsum += __shfl_xor_sync(0xFFFFFFFFu, lsum, 1);
    lsum += __shfl_xor_sync(0xFFFFFFFFu, lsum, 2);
    const float inv = 1.0f / lsum;

    float* ob = O + ((size_t)(b * L_ + qt * 64 + r) * H_ + h) * 64 + cb;
    #pragma unroll
    for (int j = 0; j < 16; j += 4) {
        float4 sv = *(const float4*)&Sf[r * LDF + cb + j];
        float4 v;
        v.x = sv.x * inv; v.y = sv.y * inv;
        v.z = sv.z * inv; v.w = sv.w * inv;
        *(float4*)&ob[j] = v;
    }
}

extern "C" void kernel_launch(void* const* d_in, const int* in_sizes, int n_in,
                              void* d_out, int out_size)
{
    cudaFuncSetAttribute(attn_kernel,
                         cudaFuncAttributeMaxDynamicSharedMemorySize, SM_BYTES);
    dim3 grid(L_ / 64, 32);
    attn_kernel<<<grid, 256, SM_BYTES>>>(
        (const float*)d_in[0], (const float*)d_in[1], (const float*)d_in[2],
        (const float*)d_in[3], (const float*)d_in[4], (float*)d_out);
}

// round 16
// speedup vs baseline: 1.3198x; 1.0543x over previous
#include <cuda_runtime.h>
#include <cuda_fp16.h>
#include <mma.h>

using namespace nvcuda;

constexpr int L_ = 2048, H_ = 8, GSTR = 512;
constexpr int LDH = 72;   // f16 tile leading dim (halves)
constexpr int LDF = 68;   // f32 tile leading dim
constexpr int OQH = 0,     OKH = 9216,  OVH = 18432, OPH = 27648;
constexpr int OSF = 36864, ODS = 54272;
constexpr int SM_BYTES = 54528;

// gmem f32 64x64 -> hi-only f16 tile, dense warp-level LDG. t in [0,256).
__device__ __forceinline__ void fill_hi(const float* g, __half* hi, int t)
{
    #pragma unroll
    for (int j = 0; j < 4; j++) {
        int c = j * 256 + t;               // 0..1023
        int row = c >> 4, col = (c & 15) * 4;
        float4 x = *(const float4*)(g + (size_t)row * GSTR + col);
        __align__(8) __half2 hh[2];
        hh[0] = __floats2half2_rn(x.x, x.y);
        hh[1] = __floats2half2_rn(x.z, x.w);
        *(uint2*)&hi[row * LDH + col] = *(uint2*)hh;
    }
}

__global__ void __launch_bounds__(256, 2)
attn_kernel(const float* __restrict__ Q, const float* __restrict__ K,
            const float* __restrict__ V, const float* __restrict__ tau,
            const float* __restrict__ delta, float* __restrict__ O)
{
    extern __shared__ char smc[];
    __half* Qhi = (__half*)(smc + OQH);
    __half* Khi = (__half*)(smc + OKH);
    __half* Vhi = (__half*)(smc + OVH);
    __half* Phi = (__half*)(smc + OPH);
    float*  Sf  = (float*)(smc + OSF);
    float*  Ds  = (float*)(smc + ODS);

    const int qt = (int)gridDim.x - 1 - (int)blockIdx.x;   // longest CTAs first
    const int bh = blockIdx.y, b = bh >> 3, h = bh & 7;
    const int t = threadIdx.x, w = t >> 5;
    const int wr = w >> 1, wc = w & 1;       // warp block: rows [16wr,+16), cols [32wc,+32)
    const int r = t >> 2, cb = (t & 3) * 16; // softmax: row r, cols [cb,cb+16)

    const float stl = 0.125f * tau[b];       // natural-log domain (__expf)
    const float sdl = 0.125f;

    const float* qg = Q + ((size_t)(b * L_ + qt * 64) * H_ + h) * 64;
    const float* kg = K + ((size_t)(b * L_) * H_ + h) * 64;
    const float* vg = V + ((size_t)(b * L_) * H_ + h) * 64;
    const float* dg = delta + (size_t)b * L_;

    fill_hi(qg, Qhi, t);

    wmma::fragment<wmma::accumulator, 16, 16, 16, float> oacc[2];
    wmma::fill_fragment(oacc[0], 0.0f);
    wmma::fill_fragment(oacc[1], 0.0f);
    float lsum = 0.0f;

    for (int kt = 0; kt <= qt; kt++) {
        __syncthreads();
        fill_hi(kg + (size_t)kt * 64 * GSTR, Khi, t);
        fill_hi(vg + (size_t)kt * 64 * GSTR, Vhi, t);
        if (t < 64) Ds[t] = dg[kt * 64 + t] * sdl;
        __syncthreads();

        // ---- QK^T: Qhi*Khi. Warp: 16x32 block ----
        {
            wmma::fragment<wmma::accumulator, 16, 16, 16, float> acc[2];
            wmma::fill_fragment(acc[0], 0.0f);
            wmma::fill_fragment(acc[1], 0.0f);
            #pragma unroll
            for (int k = 0; k < 4; k++) {
                wmma::fragment<wmma::matrix_a, 16, 16, 16, __half, wmma::row_major> aH;
                wmma::load_matrix_sync(aH, Qhi + wr * 16 * LDH + k * 16, LDH);
                #pragma unroll
                for (int n = 0; n < 2; n++) {
                    wmma::fragment<wmma::matrix_b, 16, 16, 16, __half, wmma::col_major> bH;
                    wmma::load_matrix_sync(bH, Khi + (wc * 32 + n * 16) * LDH + k * 16, LDH);
                    wmma::mma_sync(acc[n], aH, bH, acc[n]);
                }
            }
            wmma::store_matrix_sync(Sf + wr * 16 * LDF + wc * 32,      acc[0], LDF, wmma::mem_row_major);
            wmma::store_matrix_sync(Sf + wr * 16 * LDF + wc * 32 + 16, acc[1], LDF, wmma::mem_row_major);
        }
        __syncthreads();

        // ---- softmax (bounded logits, no max-sub): row r, cols [cb,cb+16) ----
        {
            const int qr = qt * 64 + r;
            const int s0 = kt * 64;
            const bool diag = (kt == qt);
            float psum = 0.0f;
            #pragma unroll
            for (int j = 0; j < 16; j += 4) {
                float4 sv = *(const float4*)&Sf[r * LDF + cb + j];
                float z0 = sv.x * stl + Ds[cb + j];
                float z1 = sv.y * stl + Ds[cb + j + 1];
                float z2 = sv.z * stl + Ds[cb + j + 2];
                float z3 = sv.w * stl + Ds[cb + j + 3];
                if (diag) {
                    if (s0 + cb + j     > qr) z0 = -1e30f;
                    if (s0 + cb + j + 1 > qr) z1 = -1e30f;
                    if (s0 + cb + j + 2 > qr) z2 = -1e30f;
                    if (s0 + cb + j + 3 > qr) z3 = -1e30f;
                }
                float p0 = __expf(z0), p1 = __expf(z1);
                float p2 = __expf(z2), p3 = __expf(z3);
                psum += (p0 + p1) + (p2 + p3);
                __align__(8) __half2 hp[2];
                hp[0] = __floats2half2_rn(p0, p1);
                hp[1] = __floats2half2_rn(p2, p3);
                *(uint2*)&Phi[r * LDH + cb + j] = *(uint2*)hp;
            }
            lsum += psum;
        }
        __syncthreads();

        // ---- P @ V: Phi*Vhi. Persistent O fragments ----
        #pragma unroll
        for (int k = 0; k < 4; k++) {
            wmma::fragment<wmma::matrix_a, 16, 16, 16, __half, wmma::row_major> pH;
            wmma::load_matrix_sync(pH, Phi + wr * 16 * LDH + k * 16, LDH);
            #pragma unroll
            for (int n = 0; n < 2; n++) {
                wmma::fragment<wmma::matrix_b, 16, 16, 16, __half, wmma::row_major> vH;
                wmma::load_matrix_sync(vH, Vhi + k * 16 * LDH + wc * 32 + n * 16, LDH);
                wmma::mma_sync(oacc[n], pH, vH, oacc[n]);
            }
        }
    }

    // ---- epilogue ----
    wmma::store_matrix_sync(Sf + wr * 16 * LDF + wc * 32,      oacc[0], LDF, wmma::mem_row_major);
    wmma::store_matrix_sync(Sf + wr * 16 * LDF + wc * 32 + 16, oacc[1], LDF, wmma::mem_row_major);
    __syncthreads();

    lsum += __shfl_xor_sync(0xFFFFFFFFu, lsum, 1);
    lsum += __shfl_xor_sync(0xFFFFFFFFu, lsum, 2);
    const float inv = 1.0f / lsum;

    float* ob = O + ((size_t)(b * L_ + qt * 64 + r) * H_ + h) * 64 + cb;
    #pragma unroll
    for (int j = 0; j < 16; j += 4) {
        float4 sv = *(const float4*)&Sf[r * LDF + cb + j];
        float4 v;
        v.x = sv.x * inv; v.y = sv.y * inv;
        v.z = sv.z * inv; v.w = sv.w * inv;
        *(float4*)&ob[j] = v;
    }
}

extern "C" void kernel_launch(void* const* d_in, const int* in_sizes, int n_in,
                              void* d_out, int out_size)
{
    cudaFuncSetAttribute(attn_kernel,
                         cudaFuncAttributeMaxDynamicSharedMemorySize, SM_BYTES);
    dim3 grid(L_ / 64, 32);
    attn_kernel<<<grid, 256, SM_BYTES>>>(
        (const float*)d_in[0], (const float*)d_in[1], (const float*)d_in[2],
        (const float*)d_in[3], (const float*)d_in[4], (float*)d_out);
}

// round 17
// speedup vs baseline: 1.3892x; 1.0526x over previous
#include <cuda_runtime.h>
#include <cuda_fp16.h>
#include <mma.h>

using namespace nvcuda;

constexpr int L_ = 2048, H_ = 8, GSTR = 512;
constexpr int LDH = 72;   // f16 tile leading dim (halves)
constexpr int LDF = 68;   // f32 tile leading dim
constexpr int OQH = 0,     OKH = 9216,  OVH = 18432, OPH = 27648;
constexpr int OSF = 36864, ODS = 54272;
constexpr int SM_BYTES = 54528;

// gmem f32 64x64 -> hi-only f16 tile, dense warp-level LDG. t in [0,256).
__device__ __forceinline__ void fill_hi(const float* g, __half* hi, int t)
{
    #pragma unroll
    for (int j = 0; j < 4; j++) {
        int c = j * 256 + t;               // 0..1023
        int row = c >> 4, col = (c & 15) * 4;
        float4 x = *(const float4*)(g + (size_t)row * GSTR + col);
        __align__(8) __half2 hh[2];
        hh[0] = __floats2half2_rn(x.x, x.y);
        hh[1] = __floats2half2_rn(x.z, x.w);
        *(uint2*)&hi[row * LDH + col] = *(uint2*)hh;
    }
}

// same, but scales by s before conversion (used for Q: folds tau*scale in)
__device__ __forceinline__ void fill_hi_scaled(const float* g, __half* hi, int t, float s)
{
    #pragma unroll
    for (int j = 0; j < 4; j++) {
        int c = j * 256 + t;
        int row = c >> 4, col = (c & 15) * 4;
        float4 x = *(const float4*)(g + (size_t)row * GSTR + col);
        __align__(8) __half2 hh[2];
        hh[0] = __floats2half2_rn(x.x * s, x.y * s);
        hh[1] = __floats2half2_rn(x.z * s, x.w * s);
        *(uint2*)&hi[row * LDH + col] = *(uint2*)hh;
    }
}

__global__ void __launch_bounds__(256, 2)
attn_kernel(const float* __restrict__ Q, const float* __restrict__ K,
            const float* __restrict__ V, const float* __restrict__ tau,
            const float* __restrict__ delta, float* __restrict__ O)
{
    extern __shared__ char smc[];
    __half* Qhi = (__half*)(smc + OQH);
    __half* Khi = (__half*)(smc + OKH);
    __half* Vhi = (__half*)(smc + OVH);
    __half* Phi = (__half*)(smc + OPH);
    float*  Sf  = (float*)(smc + OSF);
    float*  Ds  = (float*)(smc + ODS);

    const int qt = (int)gridDim.x - 1 - (int)blockIdx.x;   // longest CTAs first
    const int bh = blockIdx.y, b = bh >> 3, h = bh & 7;
    const int t = threadIdx.x, w = t >> 5;
    const int wr = w >> 1, wc = w & 1;       // warp block: rows [16wr,+16), cols [32wc,+32)
    const int r = t >> 2, cb = (t & 3) * 16; // softmax: row r, cols [cb,cb+16)

    const float stl = 0.125f * tau[b];       // folded into Q at fill

    const float* qg = Q + ((size_t)(b * L_ + qt * 64) * H_ + h) * 64;
    const float* kg = K + ((size_t)(b * L_) * H_ + h) * 64;
    const float* vg = V + ((size_t)(b * L_) * H_ + h) * 64;
    const float* dg = delta + (size_t)b * L_;

    fill_hi_scaled(qg, Qhi, t, stl);
    __syncthreads();

    // persistent Q A-fragments (loop-invariant)
    wmma::fragment<wmma::matrix_a, 16, 16, 16, __half, wmma::row_major> qf[4];
    #pragma unroll
    for (int k = 0; k < 4; k++)
        wmma::load_matrix_sync(qf[k], Qhi + wr * 16 * LDH + k * 16, LDH);

    wmma::fragment<wmma::accumulator, 16, 16, 16, float> oacc[2];
    wmma::fill_fragment(oacc[0], 0.0f);
    wmma::fill_fragment(oacc[1], 0.0f);
    float lsum = 0.0f;

    for (int kt = 0; kt <= qt; kt++) {
        __syncthreads();
        fill_hi(kg + (size_t)kt * 64 * GSTR, Khi, t);
        fill_hi(vg + (size_t)kt * 64 * GSTR, Vhi, t);
        if (t < 64) Ds[t] = dg[kt * 64 + t] * 0.125f;
        __syncthreads();

        // ---- QK^T: Qf*Khi. Warp: 16x32 block ----
        {
            wmma::fragment<wmma::accumulator, 16, 16, 16, float> acc[2];
            wmma::fill_fragment(acc[0], 0.0f);
            wmma::fill_fragment(acc[1], 0.0f);
            #pragma unroll
            for (int k = 0; k < 4; k++) {
                #pragma unroll
                for (int n = 0; n < 2; n++) {
                    wmma::fragment<wmma::matrix_b, 16, 16, 16, __half, wmma::col_major> bH;
                    wmma::load_matrix_sync(bH, Khi + (wc * 32 + n * 16) * LDH + k * 16, LDH);
                    wmma::mma_sync(acc[n], qf[k], bH, acc[n]);
                }
            }
            wmma::store_matrix_sync(Sf + wr * 16 * LDF + wc * 32,      acc[0], LDF, wmma::mem_row_major);
            wmma::store_matrix_sync(Sf + wr * 16 * LDF + wc * 32 + 16, acc[1], LDF, wmma::mem_row_major);
        }
        __syncthreads();

        // ---- softmax (bounded logits): row r, cols [cb,cb+16) ----
        {
            float psum = 0.0f;
            if (kt == qt) {                      // diagonal tile: masked variant
                const int qr = qt * 64 + r;
                const int s0 = kt * 64;
                #pragma unroll
                for (int j = 0; j < 16; j += 4) {
                    float4 sv = *(const float4*)&Sf[r * LDF + cb + j];
                    float z0 = sv.x + Ds[cb + j];
                    float z1 = sv.y + Ds[cb + j + 1];
                    float z2 = sv.z + Ds[cb + j + 2];
                    float z3 = sv.w + Ds[cb + j + 3];
                    if (s0 + cb + j     > qr) z0 = -1e30f;
                    if (s0 + cb + j + 1 > qr) z1 = -1e30f;
                    if (s0 + cb + j + 2 > qr) z2 = -1e30f;
                    if (s0 + cb + j + 3 > qr) z3 = -1e30f;
                    float p0 = __expf(z0), p1 = __expf(z1);
                    float p2 = __expf(z2), p3 = __expf(z3);
                    psum += (p0 + p1) + (p2 + p3);
                    __align__(8) __half2 hp[2];
                    hp[0] = __floats2half2_rn(p0, p1);
                    hp[1] = __floats2half2_rn(p2, p3);
                    *(uint2*)&Phi[r * LDH + cb + j] = *(uint2*)hp;
                }
            } else {                             // interior tile: no mask
                #pragma unroll
                for (int j = 0; j < 16; j += 4) {
                    float4 sv = *(const float4*)&Sf[r * LDF + cb + j];
                    float p0 = __expf(sv.x + Ds[cb + j]);
                    float p1 = __expf(sv.y + Ds[cb + j + 1]);
                    float p2 = __expf(sv.z + Ds[cb + j + 2]);
                    float p3 = __expf(sv.w + Ds[cb + j + 3]);
                    psum += (p0 + p1) + (p2 + p3);
                    __align__(8) __half2 hp[2];
                    hp[0] = __floats2half2_rn(p0, p1);
                    hp[1] = __floats2half2_rn(p2, p3);
                    *(uint2*)&Phi[r * LDH + cb + j] = *(uint2*)hp;
                }
            }
            lsum += psum;
        }
        __syncthreads();

        // ---- P @ V: Phi*Vhi. Persistent O fragments ----
        #pragma unroll
        for (int k = 0; k < 4; k++) {
            wmma::fragment<wmma::matrix_a, 16, 16, 16, __half, wmma::row_major> pH;
            wmma::load_matrix_sync(pH, Phi + wr * 16 * LDH + k * 16, LDH);
            #pragma unroll
            for (int n = 0; n < 2; n++) {
                wmma::fragment<wmma::matrix_b, 16, 16, 16, __half, wmma::row_major> vH;
                wmma::load_matrix_sync(vH, Vhi + k * 16 * LDH + wc * 32 + n * 16, LDH);
                wmma::mma_sync(oacc[n], pH, vH, oacc[n]);
            }
        }
    }

    // ---- epilogue ----
    wmma::store_matrix_sync(Sf + wr * 16 * LDF + wc * 32,      oacc[0], LDF, wmma::mem_row_major);
    wmma::store_matrix_sync(Sf + wr * 16 * LDF + wc * 32 + 16, oacc[1], LDF, wmma::mem_row_major);
    __syncthreads();

    lsum += __shfl_xor_sync(0xFFFFFFFFu, lsum, 1);
    lsum += __shfl_xor_sync(0xFFFFFFFFu, lsum, 2);
    const float inv = 1.0f / lsum;

    float* ob = O + ((size_t)(b * L_ + qt * 64 + r) * H_ + h) * 64 + cb;
    #pragma unroll
    for (int j = 0; j < 16; j += 4) {
        float4 sv = *(const float4*)&Sf[r * LDF + cb + j];
        float4 v;
        v.x = sv.x * inv; v.y = sv.y * inv;
        v.z = sv.z * inv; v.w = sv.w * inv;
        *(float4*)&ob[j] = v;
    }
}

extern "C" void kernel_launch(void* const* d_in, const int* in_sizes, int n_in,
                              void* d_out, int out_size)
{
    cudaFuncSetAttribute(attn_kernel,
                         cudaFuncAttributeMaxDynamicSharedMemorySize, SM_BYTES);
    dim3 grid(L_ / 64, 32);
    attn_kernel<<<grid, 256, SM_BYTES>>>(
        (const float*)d_in[0], (const float*)d_in[1], (const float*)d_in[2],
        (const float*)d_in[3], (const float*)d_in[4], (float*)d_out);
}